// round 7
// baseline (speedup 1.0000x reference)
#include <cuda_runtime.h>
#include <cstdint>

#define THREADS 256
#define UNROLL 4

// f = -W1^T ( m1 .* W2^T ( m2 .* g2 ) ),  m1/m2 = relu masks.
// Given m1 (8 bits), layer-2 preact is affine in p:  z2_j = c_j(m1).p + d_j(m1)
// and the backward force is f = -sum_j [z2_j>0] g2_j c_j(m1)  (same c vectors!).
// LUT[m1] = { c0x,c0y,c1x,c1y,c2x,c2y,c3x,c3y, d0,d1,d2,d3 }  (48 B/row, 12 KB).
__global__ __launch_bounds__(THREADS) void toy_force_kernel(
    const float4* __restrict__ pin,
    float4* __restrict__ pout,
    const float* __restrict__ W1,   // [8,2]
    const float* __restrict__ b1,   // [8]
    const float* __restrict__ W2,   // [4,8]
    const float* __restrict__ b2,   // [4]
    const float* __restrict__ W3,   // [2,4]
    int n_vec4)
{
    __shared__ __align__(16) float lut[256][12];

    // ---- per-thread weights for the main loop (7 x LDG.128) ----
    float w1[16], bb1[8], ng2[4];
    {
        const float4* v = reinterpret_cast<const float4*>(W1);
        #pragma unroll
        for (int i = 0; i < 4; i++) {
            float4 t = __ldg(&v[i]);
            w1[4*i] = t.x; w1[4*i+1] = t.y; w1[4*i+2] = t.z; w1[4*i+3] = t.w;
        }
        const float4* vb = reinterpret_cast<const float4*>(b1);
        #pragma unroll
        for (int i = 0; i < 2; i++) {
            float4 t = __ldg(&vb[i]);
            bb1[4*i] = t.x; bb1[4*i+1] = t.y; bb1[4*i+2] = t.z; bb1[4*i+3] = t.w;
        }
        const float4* v3 = reinterpret_cast<const float4*>(W3);
        float4 r0 = __ldg(&v3[0]), r1 = __ldg(&v3[1]);
        // ng2 = -(column sums of W3): folds the output negation into the final FMAs
        ng2[0] = -(r0.x + r1.x); ng2[1] = -(r0.y + r1.y);
        ng2[2] = -(r0.z + r1.z); ng2[3] = -(r0.w + r1.w);
    }

    // ---- build LUT: thread t owns mask m = t (one-time, ~100 FMA) ----
    {
        int m = threadIdx.x;
        #pragma unroll
        for (int j = 0; j < 4; j++) {
            float cx = 0.0f, cy = 0.0f, dd = __ldg(&b2[j]);
            #pragma unroll
            for (int i = 0; i < 8; i++) {
                float bit = (float)((m >> i) & 1);
                float w = __ldg(&W2[8*j + i]) * bit;
                cx = fmaf(w, w1[2*i],   cx);
                cy = fmaf(w, w1[2*i+1], cy);
                dd = fmaf(w, bb1[i],    dd);
            }
            lut[m][2*j]   = cx;
            lut[m][2*j+1] = cy;
            lut[m][8+j]   = dd;
        }
    }
    __syncthreads();

    const int chunk = THREADS * UNROLL;
    int base = blockIdx.x * chunk + threadIdx.x;

    // front-batch loads (MLP_p1 = UNROLL)
    float4 p[UNROLL];
    #pragma unroll
    for (int u = 0; u < UNROLL; u++) {
        int idx = base + u * THREADS;
        if (idx < n_vec4) p[u] = pin[idx];
    }

    #pragma unroll
    for (int u = 0; u < UNROLL; u++) {
        int idx = base + u * THREADS;
        if (idx >= n_vec4) continue;
        float4 o;

        #pragma unroll
        for (int s = 0; s < 2; s++) {
            float px = (s == 0) ? p[u].x : p[u].z;
            float py = (s == 0) ? p[u].y : p[u].w;

            // ---- layer 1: only the 8 sign bits are needed ----
            unsigned mneg = 0;   // bit i set iff z1_i < 0 (inactive)
            #pragma unroll
            for (int i = 0; i < 8; i++) {
                float z = fmaf(w1[2*i], px, fmaf(w1[2*i+1], py, bb1[i]));
                mneg |= (__float_as_uint(z) >> 31) << i;
            }
            unsigned midx = mneg ^ 255u;   // active mask

            // ---- LUT row: c (8 floats) + d (4 floats) ----
            const float4* row = reinterpret_cast<const float4*>(&lut[midx][0]);
            float4 cA = row[0];   // c0x c0y c1x c1y
            float4 cB = row[1];   // c2x c2y c3x c3y
            float4 dv = row[2];   // d0..d3

            // ---- layer 2 sign: z2_j = c_j . p + d_j ----
            float z0 = fmaf(cA.x, px, fmaf(cA.y, py, dv.x));
            float z1 = fmaf(cA.z, px, fmaf(cA.w, py, dv.y));
            float z2 = fmaf(cB.x, px, fmaf(cB.y, py, dv.z));
            float z3 = fmaf(cB.z, px, fmaf(cB.w, py, dv.w));

            // s_j = (z_j >= 0) ? -g2_j : 0   (bit-masked select, no predicates)
            int k0 = ~(__float_as_int(z0) >> 31);
            int k1 = ~(__float_as_int(z1) >> 31);
            int k2 = ~(__float_as_int(z2) >> 31);
            int k3 = ~(__float_as_int(z3) >> 31);
            float s0 = __int_as_float(__float_as_int(ng2[0]) & k0);
            float s1 = __int_as_float(__float_as_int(ng2[1]) & k1);
            float s2 = __int_as_float(__float_as_int(ng2[2]) & k2);
            float s3 = __int_as_float(__float_as_int(ng2[3]) & k3);

            // ---- force: f = sum_j s_j * c_j  (already negated via ng2) ----
            float fx = s0 * cA.x;
            float fy = s0 * cA.y;
            fx = fmaf(s1, cA.z, fx);  fy = fmaf(s1, cA.w, fy);
            fx = fmaf(s2, cB.x, fx);  fy = fmaf(s2, cB.y, fy);
            fx = fmaf(s3, cB.z, fx);  fy = fmaf(s3, cB.w, fy);

            if (s == 0) { o.x = fx; o.y = fy; }
            else        { o.z = fx; o.w = fy; }
        }
        pout[idx] = o;
    }
}

extern "C" void kernel_launch(void* const* d_in, const int* in_sizes, int n_in,
                              void* d_out, int out_size)
{
    const float4* pin = (const float4*)d_in[0];
    const float*  W1  = (const float*)d_in[1];
    const float*  b1  = (const float*)d_in[2];
    const float*  W2  = (const float*)d_in[3];
    const float*  b2  = (const float*)d_in[4];
    const float*  W3  = (const float*)d_in[5];
    float4* pout = (float4*)d_out;

    int n_floats = in_sizes[0];        // N*2
    int n_vec4   = n_floats / 4;       // 2,097,152 for N = 4,194,304

    int chunk  = THREADS * UNROLL;     // 1024
    int blocks = (n_vec4 + chunk - 1) / chunk;   // 2048

    toy_force_kernel<<<blocks, THREADS>>>(pin, pout, W1, b1, W2, b2, W3, n_vec4);
}

// round 8
// speedup vs baseline: 2.0611x; 2.0611x over previous
#include <cuda_runtime.h>
#include <cstdint>

#define THREADS 256
#define UNROLL 4
#define BLOCKS 296   // 2 resident blocks per SM on 148 SMs, persistent grid

// f = -W1^T( m1 .* W2^T( m2 .* g2 ) ) depends ONLY on the 12 mask bits.
// flut[(m2<<8)|m1] = final (fx, fy). 4096 x float2 = 32 KB smem.
__global__ __launch_bounds__(THREADS) void toy_force_kernel(
    const float4* __restrict__ pin,
    float4* __restrict__ pout,
    const float* __restrict__ W1,   // [8,2]
    const float* __restrict__ b1,   // [8]
    const float* __restrict__ W2,   // [4,8]
    const float* __restrict__ b2,   // [4]
    const float* __restrict__ W3,   // [2,4]
    int n_vec4)
{
    __shared__ __align__(16) float2 flut[4096];

    // ---- weights into registers (vectorized, L1-broadcast) ----
    float w1[16], bb1[8], w2[32], bb2[4];
    {
        const float4* v = reinterpret_cast<const float4*>(W1);
        #pragma unroll
        for (int i = 0; i < 4; i++) {
            float4 t = __ldg(&v[i]);
            w1[4*i] = t.x; w1[4*i+1] = t.y; w1[4*i+2] = t.z; w1[4*i+3] = t.w;
        }
        const float4* vb = reinterpret_cast<const float4*>(b1);
        #pragma unroll
        for (int i = 0; i < 2; i++) {
            float4 t = __ldg(&vb[i]);
            bb1[4*i] = t.x; bb1[4*i+1] = t.y; bb1[4*i+2] = t.z; bb1[4*i+3] = t.w;
        }
        const float4* v2 = reinterpret_cast<const float4*>(W2);
        #pragma unroll
        for (int i = 0; i < 8; i++) {
            float4 t = __ldg(&v2[i]);
            w2[4*i] = t.x; w2[4*i+1] = t.y; w2[4*i+2] = t.z; w2[4*i+3] = t.w;
        }
        float4 t2 = __ldg(reinterpret_cast<const float4*>(b2));
        bb2[0] = t2.x; bb2[1] = t2.y; bb2[2] = t2.z; bb2[3] = t2.w;
    }

    // ---- build force LUT: thread owns m1 = tid; writes 16 m2 variants ----
    {
        const float4* v3 = reinterpret_cast<const float4*>(W3);
        float4 r0 = __ldg(&v3[0]), r1 = __ldg(&v3[1]);
        float ng2[4] = { -(r0.x + r1.x), -(r0.y + r1.y),
                         -(r0.z + r1.z), -(r0.w + r1.w) };
        int m1 = threadIdx.x;
        // c_j(m1) = ( sum_i m1_i W2[j,i] W1[i,0], sum_i m1_i W2[j,i] W1[i,1] )
        float cx[4], cy[4];
        #pragma unroll
        for (int j = 0; j < 4; j++) {
            float ax = 0.0f, ay = 0.0f;
            #pragma unroll
            for (int i = 0; i < 8; i++) {
                float bit = (float)((m1 >> i) & 1);
                float w = w2[8*j + i] * bit;
                ax = fmaf(w, w1[2*i],   ax);
                ay = fmaf(w, w1[2*i+1], ay);
            }
            cx[j] = ax * ng2[j];   // pre-scale by -g2_j
            cy[j] = ay * ng2[j];
        }
        #pragma unroll
        for (int m2 = 0; m2 < 16; m2++) {
            float fx = 0.0f, fy = 0.0f;
            #pragma unroll
            for (int j = 0; j < 4; j++) {
                if (m2 & (1 << j)) { fx += cx[j]; fy += cy[j]; }
            }
            // layout (m2<<8)|m1: lanes write consecutive float2 -> conflict-free STS
            flut[(m2 << 8) | m1] = make_float2(fx, fy);
        }
    }
    __syncthreads();

    const int chunk = THREADS * UNROLL;
    const int stride = gridDim.x * chunk;

    for (int base = blockIdx.x * chunk + threadIdx.x;
         base < n_vec4 + THREADS * (UNROLL - 1); base += stride)
    {
        // front-batch loads (MLP_p1 = UNROLL)
        float4 p[UNROLL];
        #pragma unroll
        for (int u = 0; u < UNROLL; u++) {
            int idx = base + u * THREADS;
            if (idx < n_vec4) p[u] = pin[idx];
        }

        #pragma unroll
        for (int u = 0; u < UNROLL; u++) {
            int idx = base + u * THREADS;
            if (idx >= n_vec4) continue;
            float4 o;

            #pragma unroll
            for (int s = 0; s < 2; s++) {
                float px = (s == 0) ? p[u].x : p[u].z;
                float py = (s == 0) ? p[u].y : p[u].w;

                // layer 1: values + active-sign bits
                float h1[8];
                unsigned m1 = 0;
                #pragma unroll
                for (int i = 0; i < 8; i++) {
                    float z = fmaf(w1[2*i], px, fmaf(w1[2*i+1], py, bb1[i]));
                    m1 |= ((~__float_as_uint(z)) >> 31) << i;   // 1 iff z >= +0
                    h1[i] = fmaxf(z, 0.0f);
                }

                // layer 2: sign bits only
                unsigned m2 = 0;
                #pragma unroll
                for (int j = 0; j < 4; j++) {
                    float z = bb2[j];
                    #pragma unroll
                    for (int i = 0; i < 8; i++)
                        z = fmaf(w2[8*j + i], h1[i], z);
                    m2 |= ((~__float_as_uint(z)) >> 31) << j;
                }

                // single LDS.64: final force
                float2 f = flut[(m2 << 8) | m1];
                if (s == 0) { o.x = f.x; o.y = f.y; }
                else        { o.z = f.x; o.w = f.y; }
            }
            pout[idx] = o;
        }
    }
}

extern "C" void kernel_launch(void* const* d_in, const int* in_sizes, int n_in,
                              void* d_out, int out_size)
{
    const float4* pin = (const float4*)d_in[0];
    const float*  W1  = (const float*)d_in[1];
    const float*  b1  = (const float*)d_in[2];
    const float*  W2  = (const float*)d_in[3];
    const float*  b2  = (const float*)d_in[4];
    const float*  W3  = (const float*)d_in[5];
    float4* pout = (float4*)d_out;

    int n_floats = in_sizes[0];        // N*2
    int n_vec4   = n_floats / 4;       // 2,097,152 for N = 4,194,304

    toy_force_kernel<<<BLOCKS, THREADS>>>(pin, pout, W1, b1, W2, b2, W3, n_vec4);
}